// round 3
// baseline (speedup 1.0000x reference)
#include <cuda_runtime.h>
#include <cstdint>
#include <cstddef>

#define B_    64
#define P_    196
#define ENC_  512
#define E_    1024
#define H_    1024
#define A_    512
#define V_    20000
#define L_    25
#define T_    24
#define X_    2560
#define G4_   4096
#define KSPL  4
#define KT    32

typedef unsigned long long ull;

// ---- scratch layout (floats) ----------------------------------------------
static const size_t OFF_ATT_ENC = 0;                                // 64*196*512
static const size_t OFF_MEAN    = OFF_ATT_ENC + (size_t)B_*P_*ENC_;
static const size_t OFF_H0      = OFF_MEAN + (size_t)B_*ENC_;
static const size_t OFF_H1      = OFF_H0 + (size_t)B_*H_;
static const size_t OFF_C0      = OFF_H1 + (size_t)B_*H_;
static const size_t OFF_C1      = OFF_C0 + (size_t)B_*H_;
static const size_t OFF_ATTDEC  = OFF_C1 + (size_t)B_*H_;
static const size_t OFF_GATE    = OFF_ATTDEC + (size_t)B_*A_;
static const size_t OFF_ENERGY  = OFF_GATE + (size_t)B_*ENC_;
static const size_t OFF_ALPHA   = OFF_ENERGY + (size_t)B_*P_;
static const size_t OFF_XH      = OFF_ALPHA + (size_t)B_*P_;
static const size_t OFF_GATES   = OFF_XH + (size_t)B_*X_;
static const size_t SCRATCH_TOTAL = OFF_GATES + (size_t)KSPL*B_*G4_;

__device__ __align__(16) float g_scratch[SCRATCH_TOTAL];

// ---- helpers ---------------------------------------------------------------
__device__ __forceinline__ ull pack2(float x, float y) {
    ull r; asm("mov.b64 %0, {%1,%2};" : "=l"(r) : "f"(x), "f"(y)); return r;
}
__device__ __forceinline__ float2 unpack2(ull v) {
    float2 r; asm("mov.b64 {%0,%1}, %2;" : "=f"(r.x), "=f"(r.y) : "l"(v)); return r;
}
__device__ __forceinline__ ull ffma2(ull a, ull b, ull c) {
    ull d; asm("fma.rn.f32x2 %0, %1, %2, %3;" : "=l"(d) : "l"(a), "l"(b), "l"(c));
    return d;
}
__device__ __forceinline__ float sigm(float x) { return 1.0f / (1.0f + __expf(-x)); }

// ---------------------------------------------------------------------------
// gemm64: 64-row-resident GEMM. 256 thr: tx->4 cols, ty->8 rows. f32x2 acc.
// grid.x: col blocks (dual target split at blocksA). grid.y: K-split (bias
// must be null). grid.z: 64-row chunks. Weight rows k>=Ksw come from W*b.
// ---------------------------------------------------------------------------
__global__ void __launch_bounds__(256)
gemm64(const float* __restrict__ A, int lda,
       const float* __restrict__ Wa, const float* __restrict__ Wab,
       const float* __restrict__ biasa, float* Ca, int ldca, int Na, int ldwa, int epia,
       const float* __restrict__ Wb, const float* __restrict__ Wbb,
       const float* __restrict__ biasb, float* Cb, int ldcb, int Nb, int ldwb, int epib,
       int blocksA, int Ksw, int kcPerY)
{
    __shared__ float sA[KT][64];

    const int bx = blockIdx.x;
    const float *W, *W2, *bias; float* C; int ldc, N, ldw, epi, colbase;
    if (bx < blocksA) { W=Wa; W2=Wab; bias=biasa; C=Ca; ldc=ldca; N=Na; ldw=ldwa; epi=epia; colbase=bx*128; }
    else              { W=Wb; W2=Wbb; bias=biasb; C=Cb; ldc=ldcb; N=Nb; ldw=ldwb; epi=epib; colbase=(bx-blocksA)*128; }

    const int tx = threadIdx.x & 31;
    const int ty = threadIdx.x >> 5;
    const int c4 = colbase + tx * 4;
    const bool valid = (c4 < N);

    const float* Arow = A + (size_t)blockIdx.z * 64 * lda;
    const int kc0 = blockIdx.y * kcPerY;
    const int kc1 = kc0 + kcPerY;

    ull acc[4][4];
#pragma unroll
    for (int i = 0; i < 4; i++)
#pragma unroll
        for (int j = 0; j < 4; j++) acc[i][j] = 0ull;

    for (int kc = kc0; kc < kc1; kc++) {
        const int k0 = kc * KT;
        {
            const int t = threadIdx.x;
#pragma unroll
            for (int q = 0; q < 2; q++) {
                int idx = t * 2 + q;
                int r  = idx >> 3;
                int kq = (idx & 7) * 4;
                float4 v = *(const float4*)(Arow + (size_t)r * lda + k0 + kq);
                sA[kq + 0][r] = v.x; sA[kq + 1][r] = v.y;
                sA[kq + 2][r] = v.z; sA[kq + 3][r] = v.w;
            }
        }
        __syncthreads();

        const float* Wp; int krow0;
        if (W2 == nullptr || k0 < Ksw) { Wp = W;  krow0 = k0; }
        else                           { Wp = W2; krow0 = k0 - Ksw; }

        if (valid) {
            const float* wp = Wp + (size_t)krow0 * ldw + c4;
#pragma unroll
            for (int k = 0; k < KT; k++) {
                float4 w = *(const float4*)wp; wp += ldw;
                ull w0 = pack2(w.x, w.x), w1 = pack2(w.y, w.y);
                ull w2 = pack2(w.z, w.z), w3 = pack2(w.w, w.w);
                const ulonglong2* ap = (const ulonglong2*)&sA[k][ty * 8];
                ulonglong2 aA = ap[0], aB = ap[1];
                acc[0][0]=ffma2(aA.x,w0,acc[0][0]); acc[0][1]=ffma2(aA.x,w1,acc[0][1]);
                acc[0][2]=ffma2(aA.x,w2,acc[0][2]); acc[0][3]=ffma2(aA.x,w3,acc[0][3]);
                acc[1][0]=ffma2(aA.y,w0,acc[1][0]); acc[1][1]=ffma2(aA.y,w1,acc[1][1]);
                acc[1][2]=ffma2(aA.y,w2,acc[1][2]); acc[1][3]=ffma2(aA.y,w3,acc[1][3]);
                acc[2][0]=ffma2(aB.x,w0,acc[2][0]); acc[2][1]=ffma2(aB.x,w1,acc[2][1]);
                acc[2][2]=ffma2(aB.x,w2,acc[2][2]); acc[2][3]=ffma2(aB.x,w3,acc[2][3]);
                acc[3][0]=ffma2(aB.y,w0,acc[3][0]); acc[3][1]=ffma2(aB.y,w1,acc[3][1]);
                acc[3][2]=ffma2(aB.y,w2,acc[3][2]); acc[3][3]=ffma2(aB.y,w3,acc[3][3]);
            }
        }
        __syncthreads();
    }

    if (!valid) return;

    float4 bv = make_float4(0.f, 0.f, 0.f, 0.f);
    if (bias) bv = *(const float4*)(bias + c4);

    float* Cr = C + (size_t)(blockIdx.y + blockIdx.z) * 64 * ldc;
#pragma unroll
    for (int rp = 0; rp < 4; rp++) {
        float2 v0 = unpack2(acc[rp][0]), v1 = unpack2(acc[rp][1]);
        float2 v2 = unpack2(acc[rp][2]), v3 = unpack2(acc[rp][3]);
        int r0 = ty * 8 + rp * 2;
        float4 o0 = make_float4(v0.x+bv.x, v1.x+bv.y, v2.x+bv.z, v3.x+bv.w);
        float4 o1 = make_float4(v0.y+bv.x, v1.y+bv.y, v2.y+bv.z, v3.y+bv.w);
        if (epi == 1) {
            o0.x=sigm(o0.x); o0.y=sigm(o0.y); o0.z=sigm(o0.z); o0.w=sigm(o0.w);
            o1.x=sigm(o1.x); o1.y=sigm(o1.y); o1.z=sigm(o1.z); o1.w=sigm(o1.w);
        }
        *(float4*)(Cr + (size_t)r0 * ldc + c4)       = o0;
        *(float4*)(Cr + (size_t)(r0 + 1) * ldc + c4) = o1;
    }
}

// ---------------------------------------------------------------------------
__global__ void k_mean(float* S, const float* __restrict__ enc)
{
    int b = blockIdx.x;
    int e = blockIdx.y * 128 + threadIdx.x;
    const float* p0 = enc + (size_t)b * P_ * ENC_ + e;
    float s = 0.f;
#pragma unroll 4
    for (int p = 0; p < P_; p++) s += p0[(size_t)p * ENC_];
    S[OFF_MEAN + (size_t)b * ENC_ + e] = s * (1.0f / (float)P_);
}

__global__ void k_h0c0(float* S,
                       const float* __restrict__ Wh, const float* __restrict__ bh,
                       const float* __restrict__ Wc, const float* __restrict__ bc)
{
    int j  = blockIdx.x * 128 + threadIdx.x;   // 0..2047
    int bg = blockIdx.y;                       // 8 groups of 8 rows
    bool ish = (j < H_);
    int jj = j & (H_ - 1);
    const float* W = ish ? Wh : Wc;
    const float* mb = S + OFF_MEAN + (size_t)bg * 8 * ENC_;
    float acc[8];
#pragma unroll
    for (int i = 0; i < 8; i++) acc[i] = 0.f;
    for (int k = 0; k < ENC_; k++) {
        float w = W[(size_t)k * H_ + jj];
#pragma unroll
        for (int i = 0; i < 8; i++) acc[i] += mb[(size_t)i * ENC_ + k] * w;
    }
#pragma unroll
    for (int i = 0; i < 8; i++) {
        int b = bg * 8 + i;
        if (ish) {
            float v = acc[i] + bh[jj];
            S[OFF_H0 + (size_t)b * H_ + jj] = v;
            S[OFF_XH + (size_t)b * X_ + 1536 + jj] = v;
        } else {
            S[OFF_C0 + (size_t)b * H_ + jj] = acc[i] + bc[jj];
        }
    }
}

__global__ void k_energy(float* S, const float* __restrict__ Wf, const float* __restrict__ bf)
{
    int w    = threadIdx.x >> 5;
    int lane = threadIdx.x & 31;
    int gw   = blockIdx.x * 8 + w;             // b*196+p
    int b    = gw / P_;
    const float* row = S + OFF_ATT_ENC + (size_t)gw * A_;
    const float* ad  = S + OFF_ATTDEC + (size_t)b * A_;
    float s = 0.f;
#pragma unroll
    for (int i = 0; i < 4; i++) {
        int k = lane * 4 + i * 128;
        float4 v  = *(const float4*)(row + k);
        float4 d  = *(const float4*)(ad + k);
        float4 wv = *(const float4*)(Wf + k);
        s += fmaxf(v.x+d.x,0.f)*wv.x + fmaxf(v.y+d.y,0.f)*wv.y
           + fmaxf(v.z+d.z,0.f)*wv.z + fmaxf(v.w+d.w,0.f)*wv.w;
    }
#pragma unroll
    for (int o = 16; o; o >>= 1) s += __shfl_xor_sync(0xffffffffu, s, o);
    if (lane == 0) S[OFF_ENERGY + gw] = s + bf[0];
}

__global__ void k_softmax_emb(float* S, const int* __restrict__ caps,
                              const float* __restrict__ emb, float* out_alpha,
                              int t, int has_alphas)
{
    int b = blockIdx.x, tid = threadIdx.x;
    __shared__ float red[8], red2[8];
    const float* en = S + OFF_ENERGY + (size_t)b * P_;
    float v = (tid < P_) ? en[tid] : -3.0e38f;
    float m = v;
#pragma unroll
    for (int o = 16; o; o >>= 1) m = fmaxf(m, __shfl_xor_sync(0xffffffffu, m, o));
    if ((tid & 31) == 0) red[tid >> 5] = m;
    __syncthreads();
    if (tid < 32) {
        float x = (tid < 8) ? red[tid] : -3.0e38f;
#pragma unroll
        for (int o = 4; o; o >>= 1) x = fmaxf(x, __shfl_xor_sync(0xffffffffu, x, o));
        if (tid == 0) red[0] = x;
    }
    __syncthreads();
    float bm = red[0];
    float e = (tid < P_) ? __expf(v - bm) : 0.f;
    float s = e;
#pragma unroll
    for (int o = 16; o; o >>= 1) s += __shfl_xor_sync(0xffffffffu, s, o);
    if ((tid & 31) == 0) red2[tid >> 5] = s;
    __syncthreads();
    if (tid < 32) {
        float x = (tid < 8) ? red2[tid] : 0.f;
#pragma unroll
        for (int o = 4; o; o >>= 1) x += __shfl_xor_sync(0xffffffffu, x, o);
        if (tid == 0) red2[0] = x;
    }
    __syncthreads();
    float inv = 1.0f / red2[0];
    if (tid < P_) {
        float a = e * inv;
        S[OFF_ALPHA + (size_t)b * P_ + tid] = a;
        if (has_alphas) out_alpha[((size_t)b * T_ + t) * P_ + tid] = a;
    }
    int cap = caps[b * L_ + t];
    const float* er = emb + (size_t)cap * E_;
    float* x = S + OFF_XH + (size_t)b * X_;
    for (int j = tid; j < E_; j += 256) x[j] = er[j];
}

__global__ void k_context(float* S, const float* __restrict__ enc)
{
    int idx = blockIdx.x * 256 + threadIdx.x;
    int b = idx >> 9, e = idx & 511;
    const float* ap = S + OFF_ALPHA + (size_t)b * P_;
    const float* ep = enc + (size_t)b * P_ * ENC_ + e;
    float s = 0.f;
#pragma unroll 4
    for (int p = 0; p < P_; p++) s += ap[p] * ep[(size_t)p * ENC_];
    float g = S[OFF_GATE + (size_t)b * ENC_ + e];
    S[OFF_XH + (size_t)b * X_ + 1024 + e] = g * s;
}

__global__ void k_lstm(float* S, const float* __restrict__ cin, float* cout, float* hout,
                       const float* __restrict__ b_ih, const float* __restrict__ b_hh)
{
    int idx = blockIdx.x * 256 + threadIdx.x;
    int b = idx >> 10, j = idx & 1023;
    float gi = b_ih[j]        + b_hh[j];
    float gf = b_ih[j + 1024] + b_hh[j + 1024];
    float gg = b_ih[j + 2048] + b_hh[j + 2048];
    float go = b_ih[j + 3072] + b_hh[j + 3072];
    const float* g0 = S + OFF_GATES + (size_t)b * G4_;
#pragma unroll
    for (int s2 = 0; s2 < KSPL; s2++) {
        const float* gp = g0 + (size_t)s2 * B_ * G4_;
        gi += gp[j]; gf += gp[j + 1024]; gg += gp[j + 2048]; go += gp[j + 3072];
    }
    float co = cin[idx];
    float i_ = sigm(gi), f_ = sigm(gf), g_ = tanhf(gg), o_ = sigm(go);
    float cn = f_ * co + i_ * g_;
    float hn = o_ * tanhf(cn);
    cout[idx] = cn;
    hout[idx] = hn;
    S[OFF_XH + (size_t)b * X_ + 1536 + j] = hn;
}

// ---------------------------------------------------------------------------
extern "C" void kernel_launch(void* const* d_in, const int* in_sizes, int n_in,
                              void* d_out, int out_size)
{
    const float* enc        = (const float*)d_in[0];
    const int*   caps       = (const int*)  d_in[1];
    const float* W_enc_att  = (const float*)d_in[3];
    const float* b_enc_att  = (const float*)d_in[4];
    const float* W_dec_att  = (const float*)d_in[5];
    const float* b_dec_att  = (const float*)d_in[6];
    const float* W_full_att = (const float*)d_in[7];
    const float* b_full_att = (const float*)d_in[8];
    const float* emb_table  = (const float*)d_in[9];
    const float* W_ih       = (const float*)d_in[10];
    const float* b_ih       = (const float*)d_in[11];
    const float* W_hh       = (const float*)d_in[12];
    const float* b_hh       = (const float*)d_in[13];
    const float* W_init_h   = (const float*)d_in[14];
    const float* b_init_h   = (const float*)d_in[15];
    const float* W_init_c   = (const float*)d_in[16];
    const float* b_init_c   = (const float*)d_in[17];
    const float* W_fbeta    = (const float*)d_in[18];
    const float* b_fbeta    = (const float*)d_in[19];
    const float* W_fc       = (const float*)d_in[20];
    const float* b_fc       = (const float*)d_in[21];

    float* out = (float*)d_out;
    void* sp = nullptr;
    cudaGetSymbolAddress(&sp, g_scratch);
    float* S = (float*)sp;

    const long long pred_elems = (long long)B_ * T_ * V_;
    int has_alphas = ((long long)out_size > pred_elems) ? 1 : 0;
    float* out_alpha = out + (size_t)pred_elems;

    // setup: att_enc = enc @ W_enc_att + b  (12544x512x512), mean, h0/c0
    gemm64<<<dim3(4, 1, 196), 256>>>(enc, ENC_,
        W_enc_att, nullptr, b_enc_att, S + OFF_ATT_ENC, A_, A_, A_, 0,
        nullptr, nullptr, nullptr, nullptr, 0, 0, 0, 0,
        4, 0, ENC_ / KT);
    k_mean<<<dim3(B_, 4), 128>>>(S, enc);
    k_h0c0<<<dim3(16, 8), 128>>>(S, W_init_h, b_init_h, W_init_c, b_init_c);

    for (int t = 0; t < T_; t++) {
        float* hcur = S + ((t & 1) ? OFF_H1 : OFF_H0);
        float* ccur = S + ((t & 1) ? OFF_C1 : OFF_C0);
        float* hnxt = S + ((t & 1) ? OFF_H0 : OFF_H1);
        float* cnxt = S + ((t & 1) ? OFF_C0 : OFF_C1);

        // att_dec + fbeta gate (dual-target), K=1024
        gemm64<<<dim3(8, 1, 1), 256>>>(hcur, H_,
            W_dec_att, nullptr, b_dec_att, S + OFF_ATTDEC, A_, A_, A_, 0,
            W_fbeta,  nullptr, b_fbeta,  S + OFF_GATE,   ENC_, ENC_, ENC_, 1,
            4, 0, H_ / KT);

        k_energy<<<dim3((B_ * P_) / 8), 256>>>(S, W_full_att, b_full_att);
        k_softmax_emb<<<dim3(B_), 256>>>(S, caps, emb_table, out_alpha, t, has_alphas);
        k_context<<<dim3((B_ * ENC_) / 256), 256>>>(S, enc);

        // gates: xh(64x2560) @ [W_ih;W_hh](2560x4096), K-split=4, bias in lstm
        gemm64<<<dim3(G4_ / 128, KSPL, 1), 256>>>(S + OFF_XH, X_,
            W_ih, W_hh, nullptr, S + OFF_GATES, G4_, G4_, G4_, 0,
            nullptr, nullptr, nullptr, nullptr, 0, 0, 0, 0,
            G4_ / 128, 1536, (X_ / KT) / KSPL);

        k_lstm<<<dim3((B_ * H_) / 256), 256>>>(S, ccur, cnxt, hnxt, b_ih, b_hh);

        // preds: hnxt(64x1024) @ W_fc(1024x20000) + b_fc -> out[:, t, :]
        gemm64<<<dim3((V_ + 127) / 128, 1, 1), 256>>>(hnxt, H_,
            W_fc, nullptr, b_fc, out + (size_t)t * V_, T_ * V_, V_, V_, 0,
            nullptr, nullptr, nullptr, nullptr, 0, 0, 0, 0,
            (V_ + 127) / 128, 0, H_ / KT);
    }
}

// round 6
// speedup vs baseline: 1.0679x; 1.0679x over previous
#include <cuda_runtime.h>
#include <cstdint>
#include <cstddef>

#define B_    64
#define P_    196
#define ENC_  512
#define E_    1024
#define H_    1024
#define A_    512
#define V_    20000
#define L_    25
#define T_    24
#define X_    2560
#define G4_   4096
#define KSPL  4      /* gates K-split */
#define ASPL  8      /* attdec/fbeta K-split */
#define KT    64
#define PF    4

typedef unsigned long long ull;

// ---- scratch layout (floats) ----------------------------------------------
static const size_t OFF_ATT_ENC = 0;                                // 64*196*512
static const size_t OFF_MEAN    = OFF_ATT_ENC + (size_t)B_*P_*ENC_;
static const size_t OFF_H0      = OFF_MEAN + (size_t)B_*ENC_;
static const size_t OFF_H1      = OFF_H0 + (size_t)B_*H_;
static const size_t OFF_C0      = OFF_H1 + (size_t)B_*H_;
static const size_t OFF_C1      = OFF_C0 + (size_t)B_*H_;
static const size_t OFF_ATTDEC  = OFF_C1 + (size_t)B_*H_;
static const size_t OFF_GATE    = OFF_ATTDEC + (size_t)B_*A_;
static const size_t OFF_ENERGY  = OFF_GATE + (size_t)B_*ENC_;
static const size_t OFF_ALPHA   = OFF_ENERGY + (size_t)B_*P_;
static const size_t OFF_XH      = OFF_ALPHA + (size_t)B_*P_;
static const size_t OFF_GATES   = OFF_XH + (size_t)B_*X_;           // [KSPL][64][4096]
static const size_t OFF_APART   = OFF_GATES + (size_t)KSPL*B_*G4_;  // [ASPL][64][1024]
static const size_t SCRATCH_TOTAL = OFF_APART + (size_t)ASPL*B_*1024;

__device__ __align__(16) float g_scratch[SCRATCH_TOTAL];

// ---- helpers ---------------------------------------------------------------
__device__ __forceinline__ ull pack2(float x, float y) {
    ull r; asm("mov.b64 %0, {%1,%2};" : "=l"(r) : "f"(x), "f"(y)); return r;
}
__device__ __forceinline__ float2 unpack2(ull v) {
    float2 r; asm("mov.b64 {%0,%1}, %2;" : "=f"(r.x), "=f"(r.y) : "l"(v)); return r;
}
__device__ __forceinline__ ull ffma2(ull a, ull b, ull c) {
    ull d; asm("fma.rn.f32x2 %0, %1, %2, %3;" : "=l"(d) : "l"(a), "l"(b), "l"(c));
    return d;
}
__device__ __forceinline__ float sigm(float x) { return 1.0f / (1.0f + __expf(-x)); }

// ---------------------------------------------------------------------------
// gemm64 v2: 64-row-resident GEMM, bandwidth-oriented.
//  block 256 thr: cg = tid&15 -> 8 cols (col-pairs packed from LDG.128),
//                 rg = tid>>4 -> 4 rows (A splats staged in smem).
//  Inner iter: 2x LDG.128 (weights, prefetch ring PF=4) + 2x LDS.128 (A splats)
//              + 16x fma.rn.f32x2. No pack instructions in steady state.
//  grid.x: col blocks (dual target split at blocksA). grid.y: K-split (bias
//  must be null). grid.z: 64-row chunks. Weight rows k>=Ksw come from W*b.
// ---------------------------------------------------------------------------
__global__ void __launch_bounds__(256)
gemm64(const float* __restrict__ A, int lda,
       const float* __restrict__ Wa, const float* __restrict__ Wab,
       const float* __restrict__ biasa, float* Ca, int ldca, int Na, int ldwa, int epia,
       const float* __restrict__ Wb, const float* __restrict__ Wbb,
       const float* __restrict__ biasb, float* Cb, int ldcb, int Nb, int ldwb, int epib,
       int blocksA, int Ksw, int kcPerY)
{
    __shared__ ull sA2[KT][66];   // padded: stride 66 ull = 528B

    const int bx = blockIdx.x;
    const float *W, *W2, *bias; float* C; int ldc, N, ldw, epi, colbase;
    if (bx < blocksA) { W=Wa; W2=Wab; bias=biasa; C=Ca; ldc=ldca; N=Na; ldw=ldwa; epi=epia; colbase=bx*128; }
    else              { W=Wb; W2=Wbb; bias=biasb; C=Cb; ldc=ldcb; N=Nb; ldw=ldwb; epi=epib; colbase=(bx-blocksA)*128; }

    const int cg  = threadIdx.x & 15;
    const int rg4 = (threadIdx.x >> 4) * 4;
    const int c8  = colbase + cg * 8;
    const bool valid = (c8 < N);

    const float* Arow = A + (size_t)blockIdx.z * 64 * lda;
    const int kc0 = blockIdx.y * kcPerY;
    const int kc1 = kc0 + kcPerY;

    ull acc[4][4];
#pragma unroll
    for (int i = 0; i < 4; i++)
#pragma unroll
        for (int j = 0; j < 4; j++) acc[i][j] = 0ull;

    for (int kc = kc0; kc < kc1; kc++) {
        const int k0 = kc * KT;
        // stage A[0:64, k0:k0+KT] as splatted f32x2
        {
            const int idx4 = threadIdx.x * 4;
#pragma unroll
            for (int q = 0; q < 4; q++) {
                int idx = idx4 + q;            // 0..1023
                int r   = idx >> 4;            // 0..63
                int kq  = (idx & 15) * 4;      // 0..60
                float4 v = *(const float4*)(Arow + (size_t)r * lda + k0 + kq);
                sA2[kq + 0][r] = pack2(v.x, v.x);
                sA2[kq + 1][r] = pack2(v.y, v.y);
                sA2[kq + 2][r] = pack2(v.z, v.z);
                sA2[kq + 3][r] = pack2(v.w, v.w);
            }
        }
        __syncthreads();

        const float* Wp; int krow0;
        if (W2 == nullptr || k0 < Ksw) { Wp = W;  krow0 = k0; }
        else                           { Wp = W2; krow0 = k0 - Ksw; }

        if (valid) {
            const float* wp = Wp + (size_t)krow0 * ldw + c8;
            ulonglong2 wr0[PF], wr1[PF];
#pragma unroll
            for (int i = 0; i < PF; i++) {
                wr0[i] = *(const ulonglong2*)(wp + (size_t)i * ldw);
                wr1[i] = *(const ulonglong2*)(wp + (size_t)i * ldw + 4);
            }
#pragma unroll
            for (int k = 0; k < KT; k++) {
                ulonglong2 wA = wr0[k & (PF - 1)];
                ulonglong2 wB = wr1[k & (PF - 1)];
                if (k < KT - PF) {
                    wr0[k & (PF - 1)] = *(const ulonglong2*)(wp + (size_t)(k + PF) * ldw);
                    wr1[k & (PF - 1)] = *(const ulonglong2*)(wp + (size_t)(k + PF) * ldw + 4);
                }
                const ulonglong2* ap = (const ulonglong2*)&sA2[k][rg4];
                ulonglong2 aA = ap[0], aB = ap[1];
                acc[0][0]=ffma2(aA.x,wA.x,acc[0][0]); acc[0][1]=ffma2(aA.x,wA.y,acc[0][1]);
                acc[0][2]=ffma2(aA.x,wB.x,acc[0][2]); acc[0][3]=ffma2(aA.x,wB.y,acc[0][3]);
                acc[1][0]=ffma2(aA.y,wA.x,acc[1][0]); acc[1][1]=ffma2(aA.y,wA.y,acc[1][1]);
                acc[1][2]=ffma2(aA.y,wB.x,acc[1][2]); acc[1][3]=ffma2(aA.y,wB.y,acc[1][3]);
                acc[2][0]=ffma2(aB.x,wA.x,acc[2][0]); acc[2][1]=ffma2(aB.x,wA.y,acc[2][1]);
                acc[2][2]=ffma2(aB.x,wB.x,acc[2][2]); acc[2][3]=ffma2(aB.x,wB.y,acc[2][3]);
                acc[3][0]=ffma2(aB.y,wA.x,acc[3][0]); acc[3][1]=ffma2(aB.y,wA.y,acc[3][1]);
                acc[3][2]=ffma2(aB.y,wB.x,acc[3][2]); acc[3][3]=ffma2(aB.y,wB.y,acc[3][3]);
            }
        }
        __syncthreads();
    }

    if (!valid) return;

    float4 bv0 = make_float4(0.f,0.f,0.f,0.f), bv1 = bv0;
    if (bias) { bv0 = *(const float4*)(bias + c8); bv1 = *(const float4*)(bias + c8 + 4); }

    float* Cr = C + (size_t)(blockIdx.y + blockIdx.z) * 64 * ldc;
#pragma unroll
    for (int r = 0; r < 4; r++) {
        float2 p0 = unpack2(acc[r][0]), p1 = unpack2(acc[r][1]);
        float2 p2 = unpack2(acc[r][2]), p3 = unpack2(acc[r][3]);
        float4 o0 = make_float4(p0.x+bv0.x, p0.y+bv0.y, p1.x+bv0.z, p1.y+bv0.w);
        float4 o1 = make_float4(p2.x+bv1.x, p2.y+bv1.y, p3.x+bv1.z, p3.y+bv1.w);
        if (epi == 1) {
            o0.x=sigm(o0.x); o0.y=sigm(o0.y); o0.z=sigm(o0.z); o0.w=sigm(o0.w);
            o1.x=sigm(o1.x); o1.y=sigm(o1.y); o1.z=sigm(o1.z); o1.w=sigm(o1.w);
        }
        int row = rg4 + r;
        *(float4*)(Cr + (size_t)row * ldc + c8)     = o0;
        *(float4*)(Cr + (size_t)row * ldc + c8 + 4) = o1;
    }
}

// combine ASPL partials for att_dec (cols 0..511) + fbeta gate (cols 512..1023)
__global__ void k_att_combine(float* S, const float* __restrict__ b_dec,
                              const float* __restrict__ b_fb)
{
    int idx = blockIdx.x * 256 + threadIdx.x;   // 0 .. 64*1024-1
    int b = idx >> 10, c = idx & 1023;
    const float* ap = S + OFF_APART + (size_t)b * 1024 + c;
    float v = 0.f;
#pragma unroll
    for (int s = 0; s < ASPL; s++) v += ap[(size_t)s * B_ * 1024];
    if (c < 512) S[OFF_ATTDEC + (size_t)b * A_ + c] = v + b_dec[c];
    else         S[OFF_GATE + (size_t)b * ENC_ + (c - 512)] = sigm(v + b_fb[c - 512]);
}

// ---------------------------------------------------------------------------
__global__ void k_mean(float* S, const float* __restrict__ enc)
{
    int b = blockIdx.x;
    int e = blockIdx.y * 128 + threadIdx.x;
    const float* p0 = enc + (size_t)b * P_ * ENC_ + e;
    float s = 0.f;
#pragma unroll 4
    for (int p = 0; p < P_; p++) s += p0[(size_t)p * ENC_];
    S[OFF_MEAN + (size_t)b * ENC_ + e] = s * (1.0f / (float)P_);
}

__global__ void k_h0c0(float* S,
                       const float* __restrict__ Wh, const float* __restrict__ bh,
                       const float* __restrict__ Wc, const float* __restrict__ bc)
{
    int j  = blockIdx.x * 128 + threadIdx.x;   // 0..2047
    int bg = blockIdx.y;                       // 8 groups of 8 rows
    bool ish = (j < H_);
    int jj = j & (H_ - 1);
    const float* W = ish ? Wh : Wc;
    const float* mb = S + OFF_MEAN + (size_t)bg * 8 * ENC_;
    float acc[8];
#pragma unroll
    for (int i = 0; i < 8; i++) acc[i] = 0.f;
    for (int k = 0; k < ENC_; k++) {
        float w = W[(size_t)k * H_ + jj];
#pragma unroll
        for (int i = 0; i < 8; i++) acc[i] += mb[(size_t)i * ENC_ + k] * w;
    }
#pragma unroll
    for (int i = 0; i < 8; i++) {
        int b = bg * 8 + i;
        if (ish) {
            float v = acc[i] + bh[jj];
            S[OFF_H0 + (size_t)b * H_ + jj] = v;
            S[OFF_XH + (size_t)b * X_ + 1536 + jj] = v;
        } else {
            S[OFF_C0 + (size_t)b * H_ + jj] = acc[i] + bc[jj];
        }
    }
}

__global__ void k_energy(float* S, const float* __restrict__ Wf, const float* __restrict__ bf)
{
    int w    = threadIdx.x >> 5;
    int lane = threadIdx.x & 31;
    int gw   = blockIdx.x * 8 + w;             // b*196+p
    int b    = gw / P_;
    const float* row = S + OFF_ATT_ENC + (size_t)gw * A_;
    const float* ad  = S + OFF_ATTDEC + (size_t)b * A_;
    float s = 0.f;
#pragma unroll
    for (int i = 0; i < 4; i++) {
        int k = lane * 4 + i * 128;
        float4 v  = *(const float4*)(row + k);
        float4 d  = *(const float4*)(ad + k);
        float4 wv = *(const float4*)(Wf + k);
        s += fmaxf(v.x+d.x,0.f)*wv.x + fmaxf(v.y+d.y,0.f)*wv.y
           + fmaxf(v.z+d.z,0.f)*wv.z + fmaxf(v.w+d.w,0.f)*wv.w;
    }
#pragma unroll
    for (int o = 16; o; o >>= 1) s += __shfl_xor_sync(0xffffffffu, s, o);
    if (lane == 0) S[OFF_ENERGY + gw] = s + bf[0];
}

__global__ void k_softmax_emb(float* S, const int* __restrict__ caps,
                              const float* __restrict__ emb, float* out_alpha,
                              int t, int has_alphas)
{
    int b = blockIdx.x, tid = threadIdx.x;
    __shared__ float red[8], red2[8];
    const float* en = S + OFF_ENERGY + (size_t)b * P_;
    float v = (tid < P_) ? en[tid] : -3.0e38f;
    float m = v;
#pragma unroll
    for (int o = 16; o; o >>= 1) m = fmaxf(m, __shfl_xor_sync(0xffffffffu, m, o));
    if ((tid & 31) == 0) red[tid >> 5] = m;
    __syncthreads();
    if (tid < 32) {
        float x = (tid < 8) ? red[tid] : -3.0e38f;
#pragma unroll
        for (int o = 4; o; o >>= 1) x = fmaxf(x, __shfl_xor_sync(0xffffffffu, x, o));
        if (tid == 0) red[0] = x;
    }
    __syncthreads();
    float bm = red[0];
    float e = (tid < P_) ? __expf(v - bm) : 0.f;
    float s = e;
#pragma unroll
    for (int o = 16; o; o >>= 1) s += __shfl_xor_sync(0xffffffffu, s, o);
    if ((tid & 31) == 0) red2[tid >> 5] = s;
    __syncthreads();
    if (tid < 32) {
        float x = (tid < 8) ? red2[tid] : 0.f;
#pragma unroll
        for (int o = 4; o; o >>= 1) x += __shfl_xor_sync(0xffffffffu, x, o);
        if (tid == 0) red2[0] = x;
    }
    __syncthreads();
    float inv = 1.0f / red2[0];
    if (tid < P_) {
        float a = e * inv;
        S[OFF_ALPHA + (size_t)b * P_ + tid] = a;
        if (has_alphas) out_alpha[((size_t)b * T_ + t) * P_ + tid] = a;
    }
    int cap = caps[b * L_ + t];
    const float* er = emb + (size_t)cap * E_;
    float* x = S + OFF_XH + (size_t)b * X_;
    for (int j = tid; j < E_; j += 256) x[j] = er[j];
}

__global__ void k_context(float* S, const float* __restrict__ enc)
{
    int idx = blockIdx.x * 256 + threadIdx.x;
    int b = idx >> 9, e = idx & 511;
    const float* ap = S + OFF_ALPHA + (size_t)b * P_;
    const float* ep = enc + (size_t)b * P_ * ENC_ + e;
    float s = 0.f;
#pragma unroll 4
    for (int p = 0; p < P_; p++) s += ap[p] * ep[(size_t)p * ENC_];
    float g = S[OFF_GATE + (size_t)b * ENC_ + e];
    S[OFF_XH + (size_t)b * X_ + 1024 + e] = g * s;
}

__global__ void k_lstm(float* S, const float* __restrict__ cin, float* cout, float* hout,
                       const float* __restrict__ b_ih, const float* __restrict__ b_hh)
{
    int idx = blockIdx.x * 256 + threadIdx.x;
    int b = idx >> 10, j = idx & 1023;
    float gi = b_ih[j]        + b_hh[j];
    float gf = b_ih[j + 1024] + b_hh[j + 1024];
    float gg = b_ih[j + 2048] + b_hh[j + 2048];
    float go = b_ih[j + 3072] + b_hh[j + 3072];
    const float* g0 = S + OFF_GATES + (size_t)b * G4_;
#pragma unroll
    for (int s2 = 0; s2 < KSPL; s2++) {
        const float* gp = g0 + (size_t)s2 * B_ * G4_;
        gi += gp[j]; gf += gp[j + 1024]; gg += gp[j + 2048]; go += gp[j + 3072];
    }
    float co = cin[idx];
    float i_ = sigm(gi), f_ = sigm(gf), g_ = tanhf(gg), o_ = sigm(go);
    float cn = f_ * co + i_ * g_;
    float hn = o_ * tanhf(cn);
    cout[idx] = cn;
    hout[idx] = hn;
    S[OFF_XH + (size_t)b * X_ + 1536 + j] = hn;
}

// ---------------------------------------------------------------------------
extern "C" void kernel_launch(void* const* d_in, const int* in_sizes, int n_in,
                              void* d_out, int out_size)
{
    const float* enc        = (const float*)d_in[0];
    const int*   caps       = (const int*)  d_in[1];
    const float* W_enc_att  = (const float*)d_in[3];
    const float* b_enc_att  = (const float*)d_in[4];
    const float* W_dec_att  = (const float*)d_in[5];
    const float* b_dec_att  = (const float*)d_in[6];
    const float* W_full_att = (const float*)d_in[7];
    const float* b_full_att = (const float*)d_in[8];
    const float* emb_table  = (const float*)d_in[9];
    const float* W_ih       = (const float*)d_in[10];
    const float* b_ih       = (const float*)d_in[11];
    const float* W_hh       = (const float*)d_in[12];
    const float* b_hh       = (const float*)d_in[13];
    const float* W_init_h   = (const float*)d_in[14];
    const float* b_init_h   = (const float*)d_in[15];
    const float* W_init_c   = (const float*)d_in[16];
    const float* b_init_c   = (const float*)d_in[17];
    const float* W_fbeta    = (const float*)d_in[18];
    const float* b_fbeta    = (const float*)d_in[19];
    const float* W_fc       = (const float*)d_in[20];
    const float* b_fc       = (const float*)d_in[21];

    float* out = (float*)d_out;
    void* sp = nullptr;
    cudaGetSymbolAddress(&sp, g_scratch);
    float* S = (float*)sp;

    const long long pred_elems = (long long)B_ * T_ * V_;
    int has_alphas = ((long long)out_size > pred_elems) ? 1 : 0;
    float* out_alpha = out + (size_t)pred_elems;

    // setup: att_enc = enc @ W_enc_att + b  (12544x512x512)
    gemm64<<<dim3(4, 1, 196), 256>>>(enc, ENC_,
        W_enc_att, nullptr, b_enc_att, S + OFF_ATT_ENC, A_, A_, A_, 0,
        nullptr, nullptr, nullptr, nullptr, 0, 0, 0, 0,
        4, 0, ENC_ / KT);
    k_mean<<<dim3(B_, 4), 128>>>(S, enc);
    k_h0c0<<<dim3(16, 8), 128>>>(S, W_init_h, b_init_h, W_init_c, b_init_c);

    for (int t = 0; t < T_; t++) {
        float* hcur = S + ((t & 1) ? OFF_H1 : OFF_H0);
        float* ccur = S + ((t & 1) ? OFF_C1 : OFF_C0);
        float* hnxt = S + ((t & 1) ? OFF_H0 : OFF_H1);
        float* cnxt = S + ((t & 1) ? OFF_C0 : OFF_C1);

        // att_dec (cols 0..511) + fbeta (cols 512..1023), K=1024, K-split=8
        gemm64<<<dim3(8, ASPL, 1), 256>>>(hcur, H_,
            W_dec_att, nullptr, nullptr, S + OFF_APART,       1024, 512, A_,   0,
            W_fbeta,   nullptr, nullptr, S + OFF_APART + 512, 1024, 512, ENC_, 0,
            4, 0, (H_ / KT) / ASPL);
        k_att_combine<<<dim3((B_ * 1024) / 256), 256>>>(S, b_dec_att, b_fbeta);

        k_energy<<<dim3((B_ * P_) / 8), 256>>>(S, W_full_att, b_full_att);
        k_softmax_emb<<<dim3(B_), 256>>>(S, caps, emb_table, out_alpha, t, has_alphas);
        k_context<<<dim3((B_ * ENC_) / 256), 256>>>(S, enc);

        // gates: xh(64x2560) @ [W_ih;W_hh](2560x4096), K-split=4, bias in lstm
        gemm64<<<dim3(G4_ / 128, KSPL, 1), 256>>>(S + OFF_XH, X_,
            W_ih, W_hh, nullptr, S + OFF_GATES, G4_, G4_, G4_, 0,
            nullptr, nullptr, nullptr, nullptr, 0, 0, 0, 0,
            G4_ / 128, 1536, (X_ / KT) / KSPL);

        k_lstm<<<dim3((B_ * H_) / 256), 256>>>(S, ccur, cnxt, hnxt, b_ih, b_hh);

        // preds: hnxt(64x1024) @ W_fc(1024x20000) + b_fc -> out[:, t, :]
        gemm64<<<dim3((V_ + 127) / 128, 1, 1), 256>>>(hnxt, H_,
            W_fc, nullptr, b_fc, out + (size_t)t * V_, T_ * V_, V_, V_, 0,
            nullptr, nullptr, nullptr, nullptr, 0, 0, 0, 0,
            (V_ + 127) / 128, 0, H_ / KT);
    }
}